// round 9
// baseline (speedup 1.0000x reference)
#include <cuda_runtime.h>
#include <cstdint>

#define T_STEPS 2048
#define BATCH   4096
#define HID     4
#define LAYERS  3
#define TILE    32      // batch elems per group
#define GROUPS  2       // independent pipeline groups per block
#define D_PF    16      // x prefetch ring depth (slots)

// Fast, accurate tanh: (e^{2x}-1)/(e^{2x}+1) with ex2/rcp approx MUFUs.
// ~1e-6 rel error per evaluation; measured end-to-end rel_err 2.7e-7.
__device__ __forceinline__ float tanh_fast(float x) {
    float xc = fminf(fmaxf(x, -15.0f), 15.0f);   // keep e^{2x} finite
    float e  = __expf(2.0f * xc);                // FMUL + MUFU.EX2
    return (e - 1.0f) * __fdividef(1.0f, e + 1.0f);  // FADD,FADD,MUFU.RCP,FMUL
}

__device__ __forceinline__ uint32_t smem_u32(const void* p) {
    return (uint32_t)__cvta_generic_to_shared(p);
}
__device__ __forceinline__ void cp_async16(uint32_t dst, const void* src) {
    asm volatile("cp.async.cg.shared.global [%0], [%1], 16;" :: "r"(dst), "l"(src));
}
__device__ __forceinline__ void cp_commit() {
    asm volatile("cp.async.commit_group;");
}
template<int N>
__device__ __forceinline__ void cp_wait() {
    asm volatile("cp.async.wait_group %0;" :: "n"(N));
}
// Named barrier: one per group, 128 threads each (ids 1 and 2).
__device__ __forceinline__ void bar_group(int g) {
    asm volatile("bar.sync %0, 128;" :: "r"(g + 1) : "memory");
}

// Block layout: 8 warps = 2 independent groups of 4.
//   group g: warps 4g..4g+2 compute layers 0..2 (software-pipelined),
//            warp 4g+3 is the x loader (cp.async ring).
// Warp->SMSP map (wid%4): each of SMSP 0-2 gets 2 compute warps (different
// layers/groups), SMSP 3 gets the 2 light loader warps -> 2 warps/SMSP of
// latency hiding vs 1 in the baseline (occ 6.3%, issue 31.3%).
__global__ __launch_bounds__(256, 1)
void rnn_pipe_kernel(const float* __restrict__ x,
                     const float* __restrict__ h0,
                     const float* __restrict__ Wih,
                     const float* __restrict__ Whh,
                     const float* __restrict__ bih,
                     const float* __restrict__ bhh,
                     float* __restrict__ out)
{
    __shared__ float4 xbuf[GROUPS][D_PF][TILE];     // 16 KB x staging rings
    __shared__ float4 ybuf[GROUPS][2][2][TILE];     // [grp][producer layer][parity][lane]

    const int tid   = threadIdx.x;
    const int warp  = tid >> 5;
    const int lane  = tid & 31;
    const int grp   = warp >> 2;          // 0 or 1
    const int wig   = warp & 3;           // warp-in-group
    const int batch = blockIdx.x * (GROUPS * TILE) + grp * TILE + lane;

    if (wig == 3) {
        // ---------------- loader warp ----------------
        const float4* xg = (const float4*)x;
        #pragma unroll
        for (int k = 0; k < D_PF - 1; k++) {          // prologue: t = 0 .. D_PF-2
            cp_async16(smem_u32(&xbuf[grp][k][lane]), &xg[(size_t)k * BATCH + batch]);
            cp_commit();
        }
        cp_wait<D_PF - 2>();                           // t=0 complete
        bar_group(grp);
        for (int i = 0; i < T_STEPS + 2; i++) {
            int t = i + D_PF - 1;
            if (t < T_STEPS) {
                cp_async16(smem_u32(&xbuf[grp][t % D_PF][lane]),
                           &xg[(size_t)t * BATCH + batch]);
                cp_commit();
                cp_wait<D_PF - 2>();   // group for t=i+1 is done before this bar
            } else {
                cp_wait<0>();          // drain tail
            }
            bar_group(grp);
        }
    } else {
        // ---------------- compute warp: layer l = wig ----------------
        const int l = wig;
        float wih[4][4], whh[4][4], bb[4], h[4];
        #pragma unroll
        for (int c = 0; c < 4; c++) {
            #pragma unroll
            for (int j = 0; j < 4; j++) {
                wih[c][j] = Wih[l * 16 + c * 4 + j];
                whh[c][j] = Whh[l * 16 + c * 4 + j];
            }
            bb[c] = bih[l * 4 + c] + bhh[l * 4 + c];
        }
        {
            float4 hv = ((const float4*)h0)[(size_t)l * BATCH + batch];
            h[0] = hv.x; h[1] = hv.y; h[2] = hv.z; h[3] = hv.w;
        }
        bar_group(grp);   // matches loader prologue sync

        for (int i = 0; i < T_STEPS + 2; i++) {
            int t = i - l;
            if (t >= 0 && t < T_STEPS) {
                float4 in;
                if (l == 0) in = xbuf[grp][t % D_PF][lane];
                else        in = ybuf[grp][l - 1][i & 1][lane];

                float a[4];
                #pragma unroll
                for (int c = 0; c < 4; c++) {
                    float s = bb[c];
                    s = fmaf(wih[c][0], in.x, s);
                    s = fmaf(wih[c][1], in.y, s);
                    s = fmaf(wih[c][2], in.z, s);
                    s = fmaf(wih[c][3], in.w, s);
                    s = fmaf(whh[c][0], h[0], s);
                    s = fmaf(whh[c][1], h[1], s);
                    s = fmaf(whh[c][2], h[2], s);
                    s = fmaf(whh[c][3], h[3], s);
                    a[c] = s;
                }
                #pragma unroll
                for (int c = 0; c < 4; c++) h[c] = tanh_fast(a[c]);

                float4 ov = make_float4(h[0], h[1], h[2], h[3]);
                if (l == 2) ((float4*)out)[(size_t)t * BATCH + batch] = ov;
                else        ybuf[grp][l][(i + 1) & 1][lane] = ov;
            }
            bar_group(grp);
        }
    }
}

extern "C" void kernel_launch(void* const* d_in, const int* in_sizes, int n_in,
                              void* d_out, int out_size) {
    const float* x   = (const float*)d_in[0];
    const float* h0  = (const float*)d_in[1];
    const float* Wih = (const float*)d_in[2];
    const float* Whh = (const float*)d_in[3];
    const float* bih = (const float*)d_in[4];
    const float* bhh = (const float*)d_in[5];
    float* out = (float*)d_out;

    dim3 grid(BATCH / (GROUPS * TILE));   // 64 blocks
    dim3 block(256);                      // 8 warps: 2 groups x (3 layer + 1 loader)
    rnn_pipe_kernel<<<grid, block>>>(x, h0, Wih, Whh, bih, bhh, out);
}

// round 10
// speedup vs baseline: 1.6488x; 1.6488x over previous
#include <cuda_runtime.h>
#include <cstdint>

#define T_STEPS 2048
#define BATCH   4096
#define TILE    32      // batch elems per block
#define S       2       // timesteps per barrier (super-step)
#define NITER   (T_STEPS / S + 2)   // 1026: 1024 super-steps + 2 layers of skew
#define D_SLOT  16      // x ring slots (timesteps)
#define D_GRP   7       // prefetch lead in super-steps (7 groups of 2 steps)

// Lean tanh: 1 - 2/(e^{2x}+1). No clamp needed: x->+inf => e=inf => rcp=0 => 1;
// x->-inf => e=0 => rcp(1)=1 => -1. ~1e-6 rel err/eval (RCP+EX2 approx MUFUs).
__device__ __forceinline__ float tanh_fast(float x) {
    float e = __expf(2.0f * x);               // FMUL + FMUL + MUFU.EX2
    float r = __fdividef(1.0f, e + 1.0f);     // FADD + MUFU.RCP
    return fmaf(-2.0f, r, 1.0f);              // FFMA
}

__device__ __forceinline__ uint32_t smem_u32(const void* p) {
    return (uint32_t)__cvta_generic_to_shared(p);
}
__device__ __forceinline__ void cp_async16(uint32_t dst, const void* src) {
    asm volatile("cp.async.cg.shared.global [%0], [%1], 16;" :: "r"(dst), "l"(src));
}
__device__ __forceinline__ void cp_commit() {
    asm volatile("cp.async.commit_group;");
}
template<int N>
__device__ __forceinline__ void cp_wait() {
    asm volatile("cp.async.wait_group %0;" :: "n"(N));
}

// One RNN cell step with two parallel 4-FMA chains (latency 20 vs 32 serial).
__device__ __forceinline__ void cell_step(const float (&wih)[4][4],
                                          const float (&whh)[4][4],
                                          const float (&bb)[4],
                                          float4 in, float (&h)[4]) {
    float a[4];
    #pragma unroll
    for (int c = 0; c < 4; c++) {
        float sa = fmaf(wih[c][1], in.y, wih[c][0] * in.x);
        sa = fmaf(wih[c][2], in.z, sa);
        sa = fmaf(wih[c][3], in.w, sa);
        float sb = fmaf(whh[c][0], h[0], bb[c]);
        sb = fmaf(whh[c][1], h[1], sb);
        sb = fmaf(whh[c][2], h[2], sb);
        sb = fmaf(whh[c][3], h[3], sb);
        a[c] = sa + sb;
    }
    #pragma unroll
    for (int c = 0; c < 4; c++) h[c] = tanh_fast(a[c]);
}

// Proven baseline shape (275us): 128 blocks x 4 warps, __syncthreads sync.
// Warp l computes layer l for super-step i-l (2 timesteps per iteration);
// warp 3 streams x via a cp.async ring. Barrier count halved vs baseline.
__global__ __launch_bounds__(128, 1)
void rnn_pipe2_kernel(const float* __restrict__ x,
                      const float* __restrict__ h0,
                      const float* __restrict__ Wih,
                      const float* __restrict__ Whh,
                      const float* __restrict__ bih,
                      const float* __restrict__ bhh,
                      float* __restrict__ out)
{
    __shared__ float4 xbuf[D_SLOT][TILE];      // 8 KB x ring (slot = t % 16)
    __shared__ float4 ybuf[2][2][S][TILE];     // [producer layer][parity][step][lane]

    const int tid   = threadIdx.x;
    const int warp  = tid >> 5;
    const int lane  = tid & 31;
    const int batch = blockIdx.x * TILE + lane;

    if (warp == 3) {
        // ---------------- loader warp: 2 timesteps per commit group ----------
        const float4* xg = (const float4*)x;
        #pragma unroll
        for (int j = 0; j < D_GRP; j++) {      // prologue: t = 0..13
            cp_async16(smem_u32(&xbuf[2*j    ][lane]), &xg[(size_t)(2*j    ) * BATCH + batch]);
            cp_async16(smem_u32(&xbuf[2*j + 1][lane]), &xg[(size_t)(2*j + 1) * BATCH + batch]);
            cp_commit();
        }
        cp_wait<D_GRP - 1>();                  // group 0 (t=0,1) complete
        __syncthreads();
        for (int i = 0; i < NITER; i++) {
            int t = 2 * (i + D_GRP);
            if (t < T_STEPS) {
                cp_async16(smem_u32(&xbuf[ t      & (D_SLOT-1)][lane]), &xg[(size_t)(t    ) * BATCH + batch]);
                cp_async16(smem_u32(&xbuf[(t + 1) & (D_SLOT-1)][lane]), &xg[(size_t)(t + 1) * BATCH + batch]);
                cp_commit();
                cp_wait<D_GRP - 1>();          // t <= 2i+3 resident before this bar
            } else {
                cp_wait<0>();                  // drain tail
            }
            __syncthreads();
        }
    } else {
        // ---------------- compute warp: layer l = warp ----------------
        const int l = warp;
        float wih[4][4], whh[4][4], bb[4], h[4];
        #pragma unroll
        for (int c = 0; c < 4; c++) {
            #pragma unroll
            for (int j = 0; j < 4; j++) {
                wih[c][j] = Wih[l * 16 + c * 4 + j];
                whh[c][j] = Whh[l * 16 + c * 4 + j];
            }
            bb[c] = bih[l * 4 + c] + bhh[l * 4 + c];
        }
        {
            float4 hv = ((const float4*)h0)[(size_t)l * BATCH + batch];
            h[0] = hv.x; h[1] = hv.y; h[2] = hv.z; h[3] = hv.w;
        }
        __syncthreads();   // matches loader prologue sync

        for (int i = 0; i < NITER; i++) {
            int t0 = 2 * (i - l);
            if (t0 >= 0 && t0 < T_STEPS) {     // both steps in/out of range together
                float4 in0, in1;
                if (l == 0) {
                    in0 = xbuf[ t0      & (D_SLOT-1)][lane];
                    in1 = xbuf[(t0 + 1) & (D_SLOT-1)][lane];
                } else {
                    in0 = ybuf[l - 1][i & 1][0][lane];
                    in1 = ybuf[l - 1][i & 1][1][lane];
                }

                cell_step(wih, whh, bb, in0, h);
                float4 ov0 = make_float4(h[0], h[1], h[2], h[3]);
                cell_step(wih, whh, bb, in1, h);
                float4 ov1 = make_float4(h[0], h[1], h[2], h[3]);

                if (l == 2) {
                    ((float4*)out)[(size_t) t0      * BATCH + batch] = ov0;
                    ((float4*)out)[(size_t)(t0 + 1) * BATCH + batch] = ov1;
                } else {
                    ybuf[l][(i + 1) & 1][0][lane] = ov0;
                    ybuf[l][(i + 1) & 1][1][lane] = ov1;
                }
            }
            __syncthreads();
        }
    }
}

extern "C" void kernel_launch(void* const* d_in, const int* in_sizes, int n_in,
                              void* d_out, int out_size) {
    const float* x   = (const float*)d_in[0];
    const float* h0  = (const float*)d_in[1];
    const float* Wih = (const float*)d_in[2];
    const float* Whh = (const float*)d_in[3];
    const float* bih = (const float*)d_in[4];
    const float* bhh = (const float*)d_in[5];
    float* out = (float*)d_out;

    dim3 grid(BATCH / TILE);   // 128 blocks
    dim3 block(128);           // 4 warps: 3 layer warps + 1 loader warp
    rnn_pipe2_kernel<<<grid, block>>>(x, h0, Wih, Whh, bih, bhh, out);
}